// round 3
// baseline (speedup 1.0000x reference)
#include <cuda_runtime.h>

#define NN 100000
#define NE 1600000
#define ET (NE + NN)      // edges incl. self loops = 1700000
#define F  64
#define NFI 128
#define NLAY 4

// ---------------- device scratch (static globals; no runtime alloc) ----------
__device__ float d_x[NN * F];      // node state
__device__ float d_g[NN * F];      // per-layer linear output
__device__ float d_h[NN * F];      // running h accumulator
__device__ float d_e[ET];          // per-edge raw logits
__device__ int   d_deg[NN];        // zero-initialized at load; re-zeroed by k_scatter
__device__ int   d_off[NN + 1];
__device__ int   d_cur[NN];
__device__ int   d_ssrc[ET];       // src node per sorted edge slot
__device__ int   d_seid[ET];       // original edge id per sorted slot
__device__ float d_sum[F];         // zero-initialized; re-zeroed by k_stats
__device__ float d_sumsq[F];
__device__ float d_scale[F];
__device__ float d_shift[F];

__device__ __forceinline__ float lrelu(float v, float s) { return v > 0.f ? v : s * v; }

// ---------------- histogram of dst (deg starts at 0) -------------------------
__global__ void k_hist(const int* __restrict__ ei) {
    int e = blockIdx.x * blockDim.x + threadIdx.x;
    if (e < NE) atomicAdd(&d_deg[ei[NE + e]], 1);
}

// ------ single-block exclusive scan of (deg+1) -> off; also seeds cur --------
__global__ void k_scan() {
    __shared__ int warpsum[32];
    __shared__ int carry_s;
    int tid = threadIdx.x, lane = tid & 31, wid = tid >> 5;
    if (tid == 0) carry_s = 0;
    __syncthreads();
    for (int base = 0; base < NN; base += 1024) {
        int i = base + tid;
        int v = (i < NN) ? (d_deg[i] + 1) : 0;   // +1 = self loop
        int x = v;
        #pragma unroll
        for (int o = 1; o < 32; o <<= 1) {
            int t = __shfl_up_sync(0xFFFFFFFFu, x, o);
            if (lane >= o) x += t;
        }
        if (lane == 31) warpsum[wid] = x;
        __syncthreads();
        if (wid == 0) {
            int s = warpsum[lane];
            #pragma unroll
            for (int o = 1; o < 32; o <<= 1) {
                int t = __shfl_up_sync(0xFFFFFFFFu, s, o);
                if (lane >= o) s += t;
            }
            warpsum[lane] = s;
        }
        __syncthreads();
        int pre = (wid == 0) ? 0 : warpsum[wid - 1];
        int incl = x + pre;
        if (i < NN) {
            int off = carry_s + incl - v;
            d_off[i] = off;
            d_cur[i] = off;
        }
        __syncthreads();
        if (tid == 1023) carry_s += incl;
        __syncthreads();
    }
    if (threadIdx.x == 0) d_off[NN] = carry_s;
}

// ------ scatter edges into CSR slots; also re-zero deg for next replay -------
__global__ void k_scatter(const int* __restrict__ ei) {
    int idx = blockIdx.x * blockDim.x + threadIdx.x;
    if (idx < NN) d_deg[idx] = 0;
    if (idx >= ET) return;
    int s, d;
    if (idx < NE) { s = ei[idx]; d = ei[NE + idx]; }
    else          { s = idx - NE; d = s; }
    int p = atomicAdd(&d_cur[d], 1);
    d_ssrc[p] = s;
    d_seid[p] = idx;
}

// ---------------- encoder: x = lrelu(concat(xf, emb[id]) @ Win + bin) --------
__global__ void k_enc(const float* __restrict__ xf, const int* __restrict__ ids,
                      const float* __restrict__ emb, const float* __restrict__ w,
                      const float* __restrict__ b) {
    __shared__ float Wsm[NFI * F];
    __shared__ float Xin[16 * NFI];
    int tid = threadIdx.x;
    for (int k = tid; k < NFI * F; k += 256) Wsm[k] = w[k];
    int node0 = blockIdx.x * 16;
    for (int k = tid; k < 16 * NFI; k += 256) {
        int nl = k >> 7, kk = k & 127;
        int node = node0 + nl;
        float v = 0.f;
        if (node < NN) {
            if (kk < 124) v = xf[node * 124 + kk];
            else          v = emb[ids[node] * 4 + (kk - 124)];
        }
        Xin[k] = v;
    }
    __syncthreads();
    int f = tid & 63, g = tid >> 6;
    float bb = b[f];
    for (int nl = g; nl < 16; nl += 4) {
        int node = node0 + nl;
        if (node >= NN) break;
        float acc = bb;
        const float* xr = &Xin[nl * NFI];
        #pragma unroll 16
        for (int k = 0; k < NFI; k++) acc += xr[k] * Wsm[k * F + f];
        d_x[node * F + f] = lrelu(acc, 0.01f);
    }
}

// ---------------- per-layer linear: g = x @ W + b ----------------------------
__global__ void k_lin(const float* __restrict__ w, const float* __restrict__ b) {
    __shared__ float Wsm[F * F];
    __shared__ float Xin[64 * F];
    int tid = threadIdx.x;
    for (int k = tid; k < F * F; k += 256) Wsm[k] = w[k];
    int node0 = blockIdx.x * 64;
    for (int k = tid; k < 64 * F; k += 256) {
        int nl = k >> 6, kk = k & 63;
        int node = node0 + nl;
        Xin[k] = (node < NN) ? d_x[node * F + kk] : 0.f;
    }
    __syncthreads();
    int f = tid & 63, g = tid >> 6;
    float bb = b[f];
    for (int nl = g; nl < 64; nl += 4) {
        int node = node0 + nl;
        if (node >= NN) break;
        float acc = bb;
        const float* xr = &Xin[nl * F];
        #pragma unroll
        for (int k = 0; k < F; k++) acc += xr[k] * Wsm[k * F + f];
        d_g[node * F + f] = acc;
    }
}

// branchless online-softmax slot update
#define UPD(m, s, ax, ay, t, v)                         \
    {                                                   \
        float nm = fmaxf(m, t);                         \
        float c  = __expf(m - nm);                      \
        float e  = __expf(t - nm);                      \
        s  = s * c + e;                                 \
        ax = ax * c + e * (v).x;                        \
        ay = ay * c + e * (v).y;                        \
        m  = nm;                                        \
    }

// ---------------- fused GATv2 edge phase: one warp per dst node --------------
// 4-way unroll with 4 independent online-softmax states merged at the end.
__global__ void __launch_bounds__(256) k_gat(const float* __restrict__ att,
                                             const float* __restrict__ cb,
                                             float* __restrict__ xs_out) {
    int w = (blockIdx.x * blockDim.x + threadIdx.x) >> 5;
    int lane = threadIdx.x & 31;
    if (w >= NN) return;
    int beg = d_off[w], end = d_off[w + 1];

    const float2* g2 = (const float2*)d_g;
    float2 a  = __ldg((const float2*)att + lane);
    float2 gd = __ldg(g2 + w * 32 + lane);

    float m0 = -1e30f, m1 = -1e30f, m2 = -1e30f, m3 = -1e30f;
    float s0 = 0.f, s1 = 0.f, s2 = 0.f, s3 = 0.f;
    float x0 = 0.f, y0 = 0.f, x1 = 0.f, y1 = 0.f;
    float x2 = 0.f, y2 = 0.f, x3 = 0.f, y3 = 0.f;

    int p = beg;
    for (; p + 3 < end; p += 4) {
        int i0 = d_ssrc[p], i1 = d_ssrc[p + 1], i2 = d_ssrc[p + 2], i3 = d_ssrc[p + 3];
        float2 v0 = __ldg(g2 + i0 * 32 + lane);
        float2 v1 = __ldg(g2 + i1 * 32 + lane);
        float2 v2 = __ldg(g2 + i2 * 32 + lane);
        float2 v3 = __ldg(g2 + i3 * 32 + lane);
        float t0 = lrelu(v0.x + gd.x, 0.2f) * a.x + lrelu(v0.y + gd.y, 0.2f) * a.y;
        float t1 = lrelu(v1.x + gd.x, 0.2f) * a.x + lrelu(v1.y + gd.y, 0.2f) * a.y;
        float t2 = lrelu(v2.x + gd.x, 0.2f) * a.x + lrelu(v2.y + gd.y, 0.2f) * a.y;
        float t3 = lrelu(v3.x + gd.x, 0.2f) * a.x + lrelu(v3.y + gd.y, 0.2f) * a.y;
        #pragma unroll
        for (int o = 16; o > 0; o >>= 1) {
            t0 += __shfl_xor_sync(0xFFFFFFFFu, t0, o);
            t1 += __shfl_xor_sync(0xFFFFFFFFu, t1, o);
            t2 += __shfl_xor_sync(0xFFFFFFFFu, t2, o);
            t3 += __shfl_xor_sync(0xFFFFFFFFu, t3, o);
        }
        float tw = (lane == 1) ? t1 : (lane == 2) ? t2 : (lane == 3) ? t3 : t0;
        if (lane < 4) d_e[p + lane] = tw;
        UPD(m0, s0, x0, y0, t0, v0);
        UPD(m1, s1, x1, y1, t1, v1);
        UPD(m2, s2, x2, y2, t2, v2);
        UPD(m3, s3, x3, y3, t3, v3);
    }
    for (; p < end; ++p) {
        int i0 = d_ssrc[p];
        float2 v0 = __ldg(g2 + i0 * 32 + lane);
        float t0 = lrelu(v0.x + gd.x, 0.2f) * a.x + lrelu(v0.y + gd.y, 0.2f) * a.y;
        #pragma unroll
        for (int o = 16; o > 0; o >>= 1) t0 += __shfl_xor_sync(0xFFFFFFFFu, t0, o);
        if (lane == 0) d_e[p] = t0;
        UPD(m0, s0, x0, y0, t0, v0);
    }

    // merge the 4 slots
    float M = fmaxf(fmaxf(m0, m1), fmaxf(m2, m3));
    float w0 = __expf(m0 - M), w1 = __expf(m1 - M);
    float w2 = __expf(m2 - M), w3 = __expf(m3 - M);
    float ssum = s0 * w0 + s1 * w1 + s2 * w2 + s3 * w3;
    float acc0 = x0 * w0 + x1 * w1 + x2 * w2 + x3 * w3;
    float acc1 = y0 * w0 + y1 * w1 + y2 * w2 + y3 * w3;
    float inv = 1.f / ssum;

    // alpha pass: scalar logit -> alpha, lanes stride over edges
    for (int q = beg + lane; q < end; q += 32)
        xs_out[d_seid[q]] = __expf(d_e[q] - M) * inv;

    float2 cbv = __ldg((const float2*)cb + lane);
    float2 xo;
    xo.x = acc0 * inv + cbv.x;
    xo.y = acc1 * inv + cbv.y;
    ((float2*)d_x)[w * 32 + lane] = xo;
}

// ---------------- GraphNorm reductions ---------------------------------------
__global__ void k_red() {
    int f = threadIdx.x & 63, grp = threadIdx.x >> 6;
    float s = 0.f, s2 = 0.f;
    for (int i = blockIdx.x * 4 + grp; i < NN; i += gridDim.x * 4) {
        float v = d_x[i * F + f];
        s += v; s2 += v * v;
    }
    __shared__ float sm[256], sm2[256];
    sm[threadIdx.x] = s; sm2[threadIdx.x] = s2;
    __syncthreads();
    if (grp == 0) {
        s  = sm[f]  + sm[64 + f]  + sm[128 + f]  + sm[192 + f];
        s2 = sm2[f] + sm2[64 + f] + sm2[128 + f] + sm2[192 + f];
        atomicAdd(&d_sum[f], s);
        atomicAdd(&d_sumsq[f], s2);
    }
}

// stats: compute scale/shift, then zero accumulators for next layer/replay
__global__ void k_stats(const float* __restrict__ gw, const float* __restrict__ gb,
                        const float* __restrict__ gms) {
    int f = threadIdx.x;
    if (f >= F) return;
    const float invn = 1.f / (float)NN;
    float mean = d_sum[f] * invn;
    float ex2  = d_sumsq[f] * invn;
    float mm   = mean * gms[f];
    float var  = ex2 - 2.f * mm * mean + mm * mm;
    float inv  = rsqrtf(var + 1e-5f);
    float sc   = inv * gw[f];
    d_scale[f] = sc;
    d_shift[f] = gb[f] - mm * sc;
    d_sum[f] = 0.f;
    d_sumsq[f] = 0.f;
}

// norm + activation + h-accumulate; on last layer writes outputs directly
__global__ void k_norm(int first, float* __restrict__ outx, float* __restrict__ outh) {
    int total = NN * F;
    for (int i = blockIdx.x * blockDim.x + threadIdx.x; i < total;
         i += gridDim.x * blockDim.x) {
        int f = i & 63;
        float v = d_x[i] * d_scale[f] + d_shift[f];
        v = lrelu(v, 0.01f);
        float hv = first ? 0.5f * v : d_h[i] + 0.5f * v;
        if (outx) {
            outx[i] = v;
            outh[i] = hv;
        } else {
            d_x[i] = v;
            d_h[i] = hv;
        }
    }
}

// ---------------- launch ------------------------------------------------------
extern "C" void kernel_launch(void* const* d_in, const int* in_sizes, int n_in,
                              void* d_out, int out_size) {
    const float* x_feat   = (const float*)d_in[0];
    const int*   node_ids = (const int*)  d_in[1];
    const int*   edge_idx = (const int*)  d_in[2];
    const float* emb      = (const float*)d_in[3];
    const float* w_in     = (const float*)d_in[4];
    const float* b_in     = (const float*)d_in[5];
    const float* lin_w    = (const float*)d_in[6];
    const float* lin_b    = (const float*)d_in[7];
    const float* att      = (const float*)d_in[8];
    const float* conv_b   = (const float*)d_in[9];
    const float* gn_w     = (const float*)d_in[10];
    const float* gn_b     = (const float*)d_in[11];
    const float* gn_ms    = (const float*)d_in[12];
    float* out = (float*)d_out;

    // preprocessing: CSR by dst (incl. self loops)
    k_hist<<<(NE + 255) / 256, 256>>>(edge_idx);
    k_scan<<<1, 1024>>>();
    k_scatter<<<(ET + 255) / 256, 256>>>(edge_idx);

    // encoder
    k_enc<<<(NN + 15) / 16, 256>>>(x_feat, node_ids, emb, w_in, b_in);

    for (int l = 0; l < NLAY; l++) {
        k_lin<<<(NN + 63) / 64, 256>>>(lin_w + l * F * F, lin_b + l * F);
        k_gat<<<(NN + 7) / 8, 256>>>(att + l * F, conv_b + l * F,
                                     out + 2 * NN * F + (size_t)l * ET);
        k_red<<<592, 256>>>();
        k_stats<<<1, 64>>>(gn_w + l * F, gn_b + l * F, gn_ms + l * F);
        int last = (l == NLAY - 1);
        k_norm<<<2048, 256>>>(l == 0 ? 1 : 0,
                              last ? out : (float*)nullptr,
                              last ? out + NN * F : (float*)nullptr);
    }

    (void)in_sizes; (void)n_in; (void)out_size;
}

// round 4
// speedup vs baseline: 1.2619x; 1.2619x over previous
#include <cuda_runtime.h>

#define NN 100000
#define NE 1600000
#define ET (NE + NN)      // edges incl. self loops = 1700000
#define F  64
#define NFI 128
#define NLAY 4

// ---------------- device scratch (static globals; no runtime alloc) ----------
__device__ float d_x[NN * F];      // node state
__device__ float d_g[NN * F];      // per-layer linear output
__device__ float d_h[NN * F];      // running h accumulator
__device__ float d_e[ET];          // per-edge raw logits
__device__ int   d_deg[NN];        // zero-initialized at load; re-zeroed by k_scatter
__device__ int   d_off[NN + 1];
__device__ int   d_cur[NN];
__device__ int   d_ssrc[ET];       // src node per sorted edge slot
__device__ int   d_seid[ET];       // original edge id per sorted slot
__device__ float d_sum[F];         // zero-initialized; re-zeroed by k_stats
__device__ float d_sumsq[F];
__device__ float d_scale[F];
__device__ float d_shift[F];

__device__ __forceinline__ float lrelu(float v, float s) { return v > 0.f ? v : s * v; }

// ---------------- histogram of dst (deg starts at 0) -------------------------
__global__ void k_hist(const int* __restrict__ ei) {
    int e = blockIdx.x * blockDim.x + threadIdx.x;
    if (e < NE) atomicAdd(&d_deg[ei[NE + e]], 1);
}

// ------ single-block exclusive scan of (deg+1) -> off; also seeds cur --------
__global__ void k_scan() {
    __shared__ int warpsum[32];
    __shared__ int carry_s;
    int tid = threadIdx.x, lane = tid & 31, wid = tid >> 5;
    if (tid == 0) carry_s = 0;
    __syncthreads();
    for (int base = 0; base < NN; base += 1024) {
        int i = base + tid;
        int v = (i < NN) ? (d_deg[i] + 1) : 0;   // +1 = self loop
        int x = v;
        #pragma unroll
        for (int o = 1; o < 32; o <<= 1) {
            int t = __shfl_up_sync(0xFFFFFFFFu, x, o);
            if (lane >= o) x += t;
        }
        if (lane == 31) warpsum[wid] = x;
        __syncthreads();
        if (wid == 0) {
            int s = warpsum[lane];
            #pragma unroll
            for (int o = 1; o < 32; o <<= 1) {
                int t = __shfl_up_sync(0xFFFFFFFFu, s, o);
                if (lane >= o) s += t;
            }
            warpsum[lane] = s;
        }
        __syncthreads();
        int pre = (wid == 0) ? 0 : warpsum[wid - 1];
        int incl = x + pre;
        if (i < NN) {
            int off = carry_s + incl - v;
            d_off[i] = off;
            d_cur[i] = off;
        }
        __syncthreads();
        if (tid == 1023) carry_s += incl;
        __syncthreads();
    }
    if (threadIdx.x == 0) d_off[NN] = carry_s;
}

// ------ scatter edges into CSR slots; also re-zero deg for next replay -------
__global__ void k_scatter(const int* __restrict__ ei) {
    int idx = blockIdx.x * blockDim.x + threadIdx.x;
    if (idx < NN) d_deg[idx] = 0;
    if (idx >= ET) return;
    int s, d;
    if (idx < NE) { s = ei[idx]; d = ei[NE + idx]; }
    else          { s = idx - NE; d = s; }
    int p = atomicAdd(&d_cur[d], 1);
    d_ssrc[p] = s;
    d_seid[p] = idx;
}

// ---------------- encoder: x = lrelu(concat(xf, emb[id]) @ Win + bin) --------
// 32 nodes/block (NN % 32 == 0). Register-blocked: 8 nodes x 1 feature per
// thread, k stepped by 4 with float4 X loads -> FMA-bound instead of LDS-bound.
__global__ void __launch_bounds__(256) k_enc(
        const float* __restrict__ xf, const int* __restrict__ ids,
        const float* __restrict__ emb, const float* __restrict__ w,
        const float* __restrict__ b) {
    __shared__ float Wsm[NFI * F];      // 32 KB
    __shared__ float Xin[32 * NFI];     // 16 KB
    int tid = threadIdx.x;
    for (int k = tid; k < NFI * F; k += 256) Wsm[k] = w[k];
    int node0 = blockIdx.x * 32;
    for (int k = tid; k < 32 * NFI; k += 256) {
        int nl = k >> 7, kk = k & 127;
        int node = node0 + nl;
        Xin[k] = (kk < 124) ? xf[node * 124 + kk]
                            : emb[ids[node] * 4 + (kk - 124)];
    }
    __syncthreads();
    int f = tid & 63, g = tid >> 6;
    float bb = b[f];
    float acc[8];
    #pragma unroll
    for (int j = 0; j < 8; j++) acc[j] = bb;
    const float4* X4 = (const float4*)(&Xin[g * 8 * NFI]);
    #pragma unroll 4
    for (int k4 = 0; k4 < NFI / 4; k4++) {
        float w0 = Wsm[(4 * k4 + 0) * F + f];
        float w1 = Wsm[(4 * k4 + 1) * F + f];
        float w2 = Wsm[(4 * k4 + 2) * F + f];
        float w3 = Wsm[(4 * k4 + 3) * F + f];
        #pragma unroll
        for (int j = 0; j < 8; j++) {
            float4 xv = X4[j * (NFI / 4) + k4];
            acc[j] += xv.x * w0 + xv.y * w1 + xv.z * w2 + xv.w * w3;
        }
    }
    #pragma unroll
    for (int j = 0; j < 8; j++)
        d_x[(node0 + g * 8 + j) * F + f] = lrelu(acc[j], 0.01f);
}

// ---------------- per-layer linear: g = x @ W + b ----------------------------
// Same register-blocked structure, K = 64.
__global__ void __launch_bounds__(256) k_lin(const float* __restrict__ w,
                                             const float* __restrict__ b) {
    __shared__ float Wsm[F * F];        // 16 KB
    __shared__ float Xin[32 * F];       // 8 KB
    int tid = threadIdx.x;
    for (int k = tid; k < F * F; k += 256) Wsm[k] = w[k];
    int node0 = blockIdx.x * 32;
    for (int k = tid; k < 32 * F; k += 256)
        Xin[k] = d_x[node0 * F + k];
    __syncthreads();
    int f = tid & 63, g = tid >> 6;
    float bb = b[f];
    float acc[8];
    #pragma unroll
    for (int j = 0; j < 8; j++) acc[j] = bb;
    const float4* X4 = (const float4*)(&Xin[g * 8 * F]);
    #pragma unroll 4
    for (int k4 = 0; k4 < F / 4; k4++) {
        float w0 = Wsm[(4 * k4 + 0) * F + f];
        float w1 = Wsm[(4 * k4 + 1) * F + f];
        float w2 = Wsm[(4 * k4 + 2) * F + f];
        float w3 = Wsm[(4 * k4 + 3) * F + f];
        #pragma unroll
        for (int j = 0; j < 8; j++) {
            float4 xv = X4[j * (F / 4) + k4];
            acc[j] += xv.x * w0 + xv.y * w1 + xv.z * w2 + xv.w * w3;
        }
    }
    #pragma unroll
    for (int j = 0; j < 8; j++)
        d_g[(node0 + g * 8 + j) * F + f] = acc[j];
}

// ---------------- fused GATv2 edge phase: one warp per dst node --------------
// Online softmax: single gather of g[src]; raw logits stashed for alpha pass.
__global__ void k_gat(const float* __restrict__ att, const float* __restrict__ cb,
                      float* __restrict__ xs_out) {
    int w = (blockIdx.x * blockDim.x + threadIdx.x) >> 5;
    int lane = threadIdx.x & 31;
    if (w >= NN) return;
    int beg = d_off[w], end = d_off[w + 1];

    const float2* g2 = (const float2*)d_g;
    float2 a  = __ldg((const float2*)att + lane);
    float2 gd = __ldg(g2 + w * 32 + lane);

    float m = -1e30f;
    float ssum = 0.f;
    float acc0 = 0.f, acc1 = 0.f;

    int p = beg;
    for (; p + 1 < end; p += 2) {
        int s0 = d_ssrc[p], s1 = d_ssrc[p + 1];
        float2 v0 = __ldg(g2 + s0 * 32 + lane);
        float2 v1 = __ldg(g2 + s1 * 32 + lane);
        float t0 = lrelu(v0.x + gd.x, 0.2f) * a.x + lrelu(v0.y + gd.y, 0.2f) * a.y;
        float t1 = lrelu(v1.x + gd.x, 0.2f) * a.x + lrelu(v1.y + gd.y, 0.2f) * a.y;
        #pragma unroll
        for (int o = 16; o > 0; o >>= 1) {
            t0 += __shfl_xor_sync(0xFFFFFFFFu, t0, o);
            t1 += __shfl_xor_sync(0xFFFFFFFFu, t1, o);
        }
        if (lane == 0) { d_e[p] = t0; d_e[p + 1] = t1; }
        if (t0 > m) {
            float c = __expf(m - t0);
            ssum *= c; acc0 *= c; acc1 *= c; m = t0;
            ssum += 1.f; acc0 += v0.x; acc1 += v0.y;
        } else {
            float e0 = __expf(t0 - m);
            ssum += e0; acc0 += e0 * v0.x; acc1 += e0 * v0.y;
        }
        if (t1 > m) {
            float c = __expf(m - t1);
            ssum *= c; acc0 *= c; acc1 *= c; m = t1;
            ssum += 1.f; acc0 += v1.x; acc1 += v1.y;
        } else {
            float e1 = __expf(t1 - m);
            ssum += e1; acc0 += e1 * v1.x; acc1 += e1 * v1.y;
        }
    }
    if (p < end) {
        int s0 = d_ssrc[p];
        float2 v0 = __ldg(g2 + s0 * 32 + lane);
        float t0 = lrelu(v0.x + gd.x, 0.2f) * a.x + lrelu(v0.y + gd.y, 0.2f) * a.y;
        #pragma unroll
        for (int o = 16; o > 0; o >>= 1) t0 += __shfl_xor_sync(0xFFFFFFFFu, t0, o);
        if (lane == 0) d_e[p] = t0;
        if (t0 > m) {
            float c = __expf(m - t0);
            ssum *= c; acc0 *= c; acc1 *= c; m = t0;
            ssum += 1.f; acc0 += v0.x; acc1 += v0.y;
        } else {
            float e0 = __expf(t0 - m);
            ssum += e0; acc0 += e0 * v0.x; acc1 += e0 * v0.y;
        }
    }

    float inv = 1.f / ssum;

    // alpha pass: scalar logit -> alpha, lanes stride over edges
    for (int q = beg + lane; q < end; q += 32)
        xs_out[d_seid[q]] = __expf(d_e[q] - m) * inv;

    float2 cbv = __ldg((const float2*)cb + lane);
    float2 xo;
    xo.x = acc0 * inv + cbv.x;
    xo.y = acc1 * inv + cbv.y;
    ((float2*)d_x)[w * 32 + lane] = xo;
}

// ---------------- GraphNorm reductions ---------------------------------------
__global__ void k_red() {
    int f = threadIdx.x & 63, grp = threadIdx.x >> 6;
    float s = 0.f, s2 = 0.f;
    for (int i = blockIdx.x * 4 + grp; i < NN; i += gridDim.x * 4) {
        float v = d_x[i * F + f];
        s += v; s2 += v * v;
    }
    __shared__ float sm[256], sm2[256];
    sm[threadIdx.x] = s; sm2[threadIdx.x] = s2;
    __syncthreads();
    if (grp == 0) {
        s  = sm[f]  + sm[64 + f]  + sm[128 + f]  + sm[192 + f];
        s2 = sm2[f] + sm2[64 + f] + sm2[128 + f] + sm2[192 + f];
        atomicAdd(&d_sum[f], s);
        atomicAdd(&d_sumsq[f], s2);
    }
}

// stats: compute scale/shift, then zero accumulators for next layer/replay
__global__ void k_stats(const float* __restrict__ gw, const float* __restrict__ gb,
                        const float* __restrict__ gms) {
    int f = threadIdx.x;
    if (f >= F) return;
    const float invn = 1.f / (float)NN;
    float mean = d_sum[f] * invn;
    float ex2  = d_sumsq[f] * invn;
    float mm   = mean * gms[f];
    float var  = ex2 - 2.f * mm * mean + mm * mm;
    float inv  = rsqrtf(var + 1e-5f);
    float sc   = inv * gw[f];
    d_scale[f] = sc;
    d_shift[f] = gb[f] - mm * sc;
    d_sum[f] = 0.f;
    d_sumsq[f] = 0.f;
}

// norm + activation + h-accumulate; on last layer writes outputs directly
__global__ void k_norm(int first, float* __restrict__ outx, float* __restrict__ outh) {
    int total = NN * F;
    for (int i = blockIdx.x * blockDim.x + threadIdx.x; i < total;
         i += gridDim.x * blockDim.x) {
        int f = i & 63;
        float v = d_x[i] * d_scale[f] + d_shift[f];
        v = lrelu(v, 0.01f);
        float hv = first ? 0.5f * v : d_h[i] + 0.5f * v;
        if (outx) {
            outx[i] = v;
            outh[i] = hv;
        } else {
            d_x[i] = v;
            d_h[i] = hv;
        }
    }
}

// ---------------- launch ------------------------------------------------------
extern "C" void kernel_launch(void* const* d_in, const int* in_sizes, int n_in,
                              void* d_out, int out_size) {
    const float* x_feat   = (const float*)d_in[0];
    const int*   node_ids = (const int*)  d_in[1];
    const int*   edge_idx = (const int*)  d_in[2];
    const float* emb      = (const float*)d_in[3];
    const float* w_in     = (const float*)d_in[4];
    const float* b_in     = (const float*)d_in[5];
    const float* lin_w    = (const float*)d_in[6];
    const float* lin_b    = (const float*)d_in[7];
    const float* att      = (const float*)d_in[8];
    const float* conv_b   = (const float*)d_in[9];
    const float* gn_w     = (const float*)d_in[10];
    const float* gn_b     = (const float*)d_in[11];
    const float* gn_ms    = (const float*)d_in[12];
    float* out = (float*)d_out;

    // preprocessing: CSR by dst (incl. self loops)
    k_hist<<<(NE + 255) / 256, 256>>>(edge_idx);
    k_scan<<<1, 1024>>>();
    k_scatter<<<(ET + 255) / 256, 256>>>(edge_idx);

    // encoder
    k_enc<<<NN / 32, 256>>>(x_feat, node_ids, emb, w_in, b_in);

    for (int l = 0; l < NLAY; l++) {
        k_lin<<<NN / 32, 256>>>(lin_w + l * F * F, lin_b + l * F);
        k_gat<<<(NN + 7) / 8, 256>>>(att + l * F, conv_b + l * F,
                                     out + 2 * NN * F + (size_t)l * ET);
        k_red<<<592, 256>>>();
        k_stats<<<1, 64>>>(gn_w + l * F, gn_b + l * F, gn_ms + l * F);
        int last = (l == NLAY - 1);
        k_norm<<<2048, 256>>>(l == 0 ? 1 : 0,
                              last ? out : (float*)nullptr,
                              last ? out + NN * F : (float*)nullptr);
    }

    (void)in_sizes; (void)n_in; (void)out_size;
}

// round 5
// speedup vs baseline: 1.4380x; 1.1396x over previous
#include <cuda_runtime.h>

#define NN 100000
#define NE 1600000
#define ET (NE + NN)      // edges incl. self loops = 1700000
#define F  64
#define NFI 128
#define NLAY 4

// ---------------- device scratch (static globals; no runtime alloc) ----------
__device__ float d_x[NN * F];      // node state
__device__ float d_g[NN * F];      // per-layer linear output
__device__ float d_h[NN * F];      // running h accumulator
__device__ float d_e[ET];          // per-edge raw logits
__device__ int   d_deg[NN];        // zero-initialized at load; re-zeroed by k_scatter
__device__ int   d_off[NN + 1];
__device__ int   d_cur[NN];
__device__ int   d_ssrc[ET];       // src node per sorted edge slot
__device__ int   d_seid[ET];       // original edge id per sorted slot
__device__ float d_sum[F];         // zero-initialized; re-zeroed by k_stats
__device__ float d_sumsq[F];
__device__ float d_scale[F];
__device__ float d_shift[F];

__device__ __forceinline__ float lrelu(float v, float s) { return v > 0.f ? v : s * v; }

// ---------------- histogram of dst (deg starts at 0) -------------------------
__global__ void k_hist(const int* __restrict__ ei) {
    int e = blockIdx.x * blockDim.x + threadIdx.x;
    if (e < NE) atomicAdd(&d_deg[ei[NE + e]], 1);
}

// ------ single-block exclusive scan of (deg+1) -> off; also seeds cur --------
__global__ void k_scan() {
    __shared__ int warpsum[32];
    __shared__ int carry_s;
    int tid = threadIdx.x, lane = tid & 31, wid = tid >> 5;
    if (tid == 0) carry_s = 0;
    __syncthreads();
    for (int base = 0; base < NN; base += 1024) {
        int i = base + tid;
        int v = (i < NN) ? (d_deg[i] + 1) : 0;   // +1 = self loop
        int x = v;
        #pragma unroll
        for (int o = 1; o < 32; o <<= 1) {
            int t = __shfl_up_sync(0xFFFFFFFFu, x, o);
            if (lane >= o) x += t;
        }
        if (lane == 31) warpsum[wid] = x;
        __syncthreads();
        if (wid == 0) {
            int s = warpsum[lane];
            #pragma unroll
            for (int o = 1; o < 32; o <<= 1) {
                int t = __shfl_up_sync(0xFFFFFFFFu, s, o);
                if (lane >= o) s += t;
            }
            warpsum[lane] = s;
        }
        __syncthreads();
        int pre = (wid == 0) ? 0 : warpsum[wid - 1];
        int incl = x + pre;
        if (i < NN) {
            int off = carry_s + incl - v;
            d_off[i] = off;
            d_cur[i] = off;
        }
        __syncthreads();
        if (tid == 1023) carry_s += incl;
        __syncthreads();
    }
    if (threadIdx.x == 0) d_off[NN] = carry_s;
}

// ------ scatter edges into CSR slots; also re-zero deg for next replay -------
__global__ void k_scatter(const int* __restrict__ ei) {
    int idx = blockIdx.x * blockDim.x + threadIdx.x;
    if (idx < NN) d_deg[idx] = 0;
    if (idx >= ET) return;
    int s, d;
    if (idx < NE) { s = ei[idx]; d = ei[NE + idx]; }
    else          { s = idx - NE; d = s; }
    int p = atomicAdd(&d_cur[d], 1);
    d_ssrc[p] = s;
    d_seid[p] = idx;
}

// ---------------- encoder: x = lrelu(concat(xf, emb[id]) @ Win + bin) --------
// 128 nodes/block, thread tile = 8 nodes x 4 features, K=128.
// bytes/FMA = 1.5 -> FMA-bound.
__global__ void __launch_bounds__(256) k_enc(
        const float* __restrict__ xf, const int* __restrict__ ids,
        const float* __restrict__ emb, const float* __restrict__ w,
        const float* __restrict__ b) {
    __shared__ float Wsm[NFI * F];       // 32 KB, row-major [k][f]
    __shared__ float Xin[128 * NFI];     // 64 KB
    int tid = threadIdx.x;
    // load W (float4, coalesced)
    {
        const float4* wg = (const float4*)w;
        float4* ws = (float4*)Wsm;
        #pragma unroll
        for (int q = tid; q < NFI * F / 4; q += 256) ws[q] = wg[q];
    }
    int node0 = blockIdx.x * 128;
    // load X rows: 32 float4 per node (31 from xf, 1 from emb)
    {
        float4* xs = (float4*)Xin;
        for (int q = tid; q < 128 * 32; q += 256) {
            int nl = q >> 5, c4 = q & 31;
            int node = node0 + nl;
            float4 v = make_float4(0.f, 0.f, 0.f, 0.f);
            if (node < NN) {
                if (c4 < 31) v = ((const float4*)(xf + (size_t)node * 124))[c4];
                else         v = ((const float4*)emb)[ids[node]];
            }
            xs[q] = v;
        }
    }
    __syncthreads();
    int f4 = tid & 15;          // feature group (4 feats)
    int ng = tid >> 4;          // node group (8 nodes)
    const float4* W4 = (const float4*)Wsm;
    const float4* X4 = (const float4*)(&Xin[ng * 8 * NFI]);
    float4 bb = ((const float4*)b)[f4];
    float4 acc[8];
    #pragma unroll
    for (int j = 0; j < 8; j++) acc[j] = bb;
    #pragma unroll 2
    for (int k4 = 0; k4 < NFI / 4; k4++) {
        float4 w0 = W4[(4 * k4 + 0) * 16 + f4];
        float4 w1 = W4[(4 * k4 + 1) * 16 + f4];
        float4 w2 = W4[(4 * k4 + 2) * 16 + f4];
        float4 w3 = W4[(4 * k4 + 3) * 16 + f4];
        #pragma unroll
        for (int j = 0; j < 8; j++) {
            float4 xv = X4[j * (NFI / 4) + k4];
            acc[j].x += xv.x * w0.x + xv.y * w1.x + xv.z * w2.x + xv.w * w3.x;
            acc[j].y += xv.x * w0.y + xv.y * w1.y + xv.z * w2.y + xv.w * w3.y;
            acc[j].z += xv.x * w0.z + xv.y * w1.z + xv.z * w2.z + xv.w * w3.z;
            acc[j].w += xv.x * w0.w + xv.y * w1.w + xv.z * w2.w + xv.w * w3.w;
        }
    }
    #pragma unroll
    for (int j = 0; j < 8; j++) {
        int node = node0 + ng * 8 + j;
        if (node < NN) {
            float4 o;
            o.x = lrelu(acc[j].x, 0.01f);
            o.y = lrelu(acc[j].y, 0.01f);
            o.z = lrelu(acc[j].z, 0.01f);
            o.w = lrelu(acc[j].w, 0.01f);
            ((float4*)d_x)[node * 16 + f4] = o;
        }
    }
}

// ---------------- per-layer linear: g = x @ W + b ----------------------------
// 128 nodes/block, thread tile = 8 nodes x 4 features, K=64.
__global__ void __launch_bounds__(256) k_lin(const float* __restrict__ w,
                                             const float* __restrict__ b) {
    __shared__ float Wsm[F * F];         // 16 KB, row-major [k][f]
    __shared__ float Xin[128 * F];       // 32 KB
    int tid = threadIdx.x;
    {
        const float4* wg = (const float4*)w;
        float4* ws = (float4*)Wsm;
        #pragma unroll
        for (int q = tid; q < F * F / 4; q += 256) ws[q] = wg[q];
    }
    int node0 = blockIdx.x * 128;
    {
        float4* xs = (float4*)Xin;
        const float4* xg = (const float4*)d_x;
        for (int q = tid; q < 128 * 16; q += 256) {
            int node = node0 + (q >> 4);
            xs[q] = (node < NN) ? xg[node0 * 16 + q]
                                : make_float4(0.f, 0.f, 0.f, 0.f);
        }
    }
    __syncthreads();
    int f4 = tid & 15;
    int ng = tid >> 4;
    const float4* W4 = (const float4*)Wsm;
    const float4* X4 = (const float4*)(&Xin[ng * 8 * F]);
    float4 bb = ((const float4*)b)[f4];
    float4 acc[8];
    #pragma unroll
    for (int j = 0; j < 8; j++) acc[j] = bb;
    #pragma unroll 2
    for (int k4 = 0; k4 < F / 4; k4++) {
        float4 w0 = W4[(4 * k4 + 0) * 16 + f4];
        float4 w1 = W4[(4 * k4 + 1) * 16 + f4];
        float4 w2 = W4[(4 * k4 + 2) * 16 + f4];
        float4 w3 = W4[(4 * k4 + 3) * 16 + f4];
        #pragma unroll
        for (int j = 0; j < 8; j++) {
            float4 xv = X4[j * (F / 4) + k4];
            acc[j].x += xv.x * w0.x + xv.y * w1.x + xv.z * w2.x + xv.w * w3.x;
            acc[j].y += xv.x * w0.y + xv.y * w1.y + xv.z * w2.y + xv.w * w3.y;
            acc[j].z += xv.x * w0.z + xv.y * w1.z + xv.z * w2.z + xv.w * w3.z;
            acc[j].w += xv.x * w0.w + xv.y * w1.w + xv.z * w2.w + xv.w * w3.w;
        }
    }
    #pragma unroll
    for (int j = 0; j < 8; j++) {
        int node = node0 + ng * 8 + j;
        if (node < NN)
            ((float4*)d_g)[node * 16 + f4] = acc[j];
    }
}

// ---------------- fused GATv2 edge phase: one warp per dst node --------------
// Online softmax: single gather of g[src]; raw logits stashed for alpha pass.
__global__ void k_gat(const float* __restrict__ att, const float* __restrict__ cb,
                      float* __restrict__ xs_out) {
    int w = (blockIdx.x * blockDim.x + threadIdx.x) >> 5;
    int lane = threadIdx.x & 31;
    if (w >= NN) return;
    int beg = d_off[w], end = d_off[w + 1];

    const float2* g2 = (const float2*)d_g;
    float2 a  = __ldg((const float2*)att + lane);
    float2 gd = __ldg(g2 + w * 32 + lane);

    float m = -1e30f;
    float ssum = 0.f;
    float acc0 = 0.f, acc1 = 0.f;

    int p = beg;
    for (; p + 1 < end; p += 2) {
        int s0 = d_ssrc[p], s1 = d_ssrc[p + 1];
        float2 v0 = __ldg(g2 + s0 * 32 + lane);
        float2 v1 = __ldg(g2 + s1 * 32 + lane);
        float t0 = lrelu(v0.x + gd.x, 0.2f) * a.x + lrelu(v0.y + gd.y, 0.2f) * a.y;
        float t1 = lrelu(v1.x + gd.x, 0.2f) * a.x + lrelu(v1.y + gd.y, 0.2f) * a.y;
        #pragma unroll
        for (int o = 16; o > 0; o >>= 1) {
            t0 += __shfl_xor_sync(0xFFFFFFFFu, t0, o);
            t1 += __shfl_xor_sync(0xFFFFFFFFu, t1, o);
        }
        if (lane == 0) { d_e[p] = t0; d_e[p + 1] = t1; }
        if (t0 > m) {
            float c = __expf(m - t0);
            ssum *= c; acc0 *= c; acc1 *= c; m = t0;
            ssum += 1.f; acc0 += v0.x; acc1 += v0.y;
        } else {
            float e0 = __expf(t0 - m);
            ssum += e0; acc0 += e0 * v0.x; acc1 += e0 * v0.y;
        }
        if (t1 > m) {
            float c = __expf(m - t1);
            ssum *= c; acc0 *= c; acc1 *= c; m = t1;
            ssum += 1.f; acc0 += v1.x; acc1 += v1.y;
        } else {
            float e1 = __expf(t1 - m);
            ssum += e1; acc0 += e1 * v1.x; acc1 += e1 * v1.y;
        }
    }
    if (p < end) {
        int s0 = d_ssrc[p];
        float2 v0 = __ldg(g2 + s0 * 32 + lane);
        float t0 = lrelu(v0.x + gd.x, 0.2f) * a.x + lrelu(v0.y + gd.y, 0.2f) * a.y;
        #pragma unroll
        for (int o = 16; o > 0; o >>= 1) t0 += __shfl_xor_sync(0xFFFFFFFFu, t0, o);
        if (lane == 0) d_e[p] = t0;
        if (t0 > m) {
            float c = __expf(m - t0);
            ssum *= c; acc0 *= c; acc1 *= c; m = t0;
            ssum += 1.f; acc0 += v0.x; acc1 += v0.y;
        } else {
            float e0 = __expf(t0 - m);
            ssum += e0; acc0 += e0 * v0.x; acc1 += e0 * v0.y;
        }
    }

    float inv = 1.f / ssum;

    // alpha pass: scalar logit -> alpha, lanes stride over edges
    for (int q = beg + lane; q < end; q += 32)
        xs_out[d_seid[q]] = __expf(d_e[q] - m) * inv;

    float2 cbv = __ldg((const float2*)cb + lane);
    float2 xo;
    xo.x = acc0 * inv + cbv.x;
    xo.y = acc1 * inv + cbv.y;
    ((float2*)d_x)[w * 32 + lane] = xo;
}

// ---------------- GraphNorm reductions ---------------------------------------
__global__ void k_red() {
    int f = threadIdx.x & 63, grp = threadIdx.x >> 6;
    float s = 0.f, s2 = 0.f;
    for (int i = blockIdx.x * 4 + grp; i < NN; i += gridDim.x * 4) {
        float v = d_x[i * F + f];
        s += v; s2 += v * v;
    }
    __shared__ float sm[256], sm2[256];
    sm[threadIdx.x] = s; sm2[threadIdx.x] = s2;
    __syncthreads();
    if (grp == 0) {
        s  = sm[f]  + sm[64 + f]  + sm[128 + f]  + sm[192 + f];
        s2 = sm2[f] + sm2[64 + f] + sm2[128 + f] + sm2[192 + f];
        atomicAdd(&d_sum[f], s);
        atomicAdd(&d_sumsq[f], s2);
    }
}

// stats: compute scale/shift, then zero accumulators for next layer/replay
__global__ void k_stats(const float* __restrict__ gw, const float* __restrict__ gb,
                        const float* __restrict__ gms) {
    int f = threadIdx.x;
    if (f >= F) return;
    const float invn = 1.f / (float)NN;
    float mean = d_sum[f] * invn;
    float ex2  = d_sumsq[f] * invn;
    float mm   = mean * gms[f];
    float var  = ex2 - 2.f * mm * mean + mm * mm;
    float inv  = rsqrtf(var + 1e-5f);
    float sc   = inv * gw[f];
    d_scale[f] = sc;
    d_shift[f] = gb[f] - mm * sc;
    d_sum[f] = 0.f;
    d_sumsq[f] = 0.f;
}

// norm + activation + h-accumulate; on last layer writes outputs directly
__global__ void k_norm(int first, float* __restrict__ outx, float* __restrict__ outh) {
    int total = NN * F;
    for (int i = blockIdx.x * blockDim.x + threadIdx.x; i < total;
         i += gridDim.x * blockDim.x) {
        int f = i & 63;
        float v = d_x[i] * d_scale[f] + d_shift[f];
        v = lrelu(v, 0.01f);
        float hv = first ? 0.5f * v : d_h[i] + 0.5f * v;
        if (outx) {
            outx[i] = v;
            outh[i] = hv;
        } else {
            d_x[i] = v;
            d_h[i] = hv;
        }
    }
}

// ---------------- launch ------------------------------------------------------
extern "C" void kernel_launch(void* const* d_in, const int* in_sizes, int n_in,
                              void* d_out, int out_size) {
    const float* x_feat   = (const float*)d_in[0];
    const int*   node_ids = (const int*)  d_in[1];
    const int*   edge_idx = (const int*)  d_in[2];
    const float* emb      = (const float*)d_in[3];
    const float* w_in     = (const float*)d_in[4];
    const float* b_in     = (const float*)d_in[5];
    const float* lin_w    = (const float*)d_in[6];
    const float* lin_b    = (const float*)d_in[7];
    const float* att      = (const float*)d_in[8];
    const float* conv_b   = (const float*)d_in[9];
    const float* gn_w     = (const float*)d_in[10];
    const float* gn_b     = (const float*)d_in[11];
    const float* gn_ms    = (const float*)d_in[12];
    float* out = (float*)d_out;

    // preprocessing: CSR by dst (incl. self loops)
    k_hist<<<(NE + 255) / 256, 256>>>(edge_idx);
    k_scan<<<1, 1024>>>();
    k_scatter<<<(ET + 255) / 256, 256>>>(edge_idx);

    // encoder
    k_enc<<<(NN + 127) / 128, 256>>>(x_feat, node_ids, emb, w_in, b_in);

    for (int l = 0; l < NLAY; l++) {
        k_lin<<<(NN + 127) / 128, 256>>>(lin_w + l * F * F, lin_b + l * F);
        k_gat<<<(NN + 7) / 8, 256>>>(att + l * F, conv_b + l * F,
                                     out + 2 * NN * F + (size_t)l * ET);
        k_red<<<592, 256>>>();
        k_stats<<<1, 64>>>(gn_w + l * F, gn_b + l * F, gn_ms + l * F);
        int last = (l == NLAY - 1);
        k_norm<<<2048, 256>>>(l == 0 ? 1 : 0,
                              last ? out : (float*)nullptr,
                              last ? out + NN * F : (float*)nullptr);
    }

    (void)in_sizes; (void)n_in; (void)out_size;
}